// round 10
// baseline (speedup 1.0000x reference)
#include <cuda_runtime.h>
#include <cstdint>
#include <cstddef>

// ---------------------------------------------------------------------------
// DynamicGraphBuilder: per (b,t) item: 19x19 cosine similarity -> /0.1 ->
// softmax -> top-3 keep -> threshold 1e-4 -> 0.5*(A+A^T).
// One warp per item. F staged in SMEM (4 groups of 5 rows, XOR granule
// swizzle key=2*grp). Gram via 10 upper-tri 5x5 register tiles x 2 d-halves
// (20 lanes), every operand LDS.128 = exactly 1 conflict-free wavefront.
// G aliases F (F dead after gram loop). 5 CTAs/SM.
// ---------------------------------------------------------------------------

namespace {

constexpr int kN = 19;
constexpr int kT = 2048;
constexpr int kD = 128;
constexpr int kItems = 32 * kT;            // 65536
constexpr int kWarpsPerCta = 4;
constexpr int kThreads = kWarpsPerCta * 32;
constexpr int kGrid = kItems / kWarpsPerCta;

constexpr float kInvTemp = 10.0f;          // 1 / 0.1
constexpr float kThresh = 1e-4f;

// Per-warp SMEM: F = 20 rows x 128 floats (row 19 zero pad), 2560 words.
// G (19 x stride 21 = 399 words) ALIASES the start of F: F is dead before
// the first G write (scatter happens after the full gram loop).
constexpr int kGS = 21;
constexpr int kWarpWords = 2560;           // 10240 B / warp, 40960 B / CTA

__device__ __forceinline__ unsigned long long ffma2(unsigned long long a,
                                                    unsigned long long b,
                                                    unsigned long long c) {
    unsigned long long d;
    asm("fma.rn.f32x2 %0, %1, %2, %3;" : "=l"(d) : "l"(a), "l"(b), "l"(c));
    return d;
}

__device__ __forceinline__ float2 unpack2(unsigned long long v) {
    float2 r;
    asm("mov.b64 {%0, %1}, %2;" : "=f"(r.x), "=f"(r.y) : "l"(v));
    return r;
}

__device__ __forceinline__ void lds128(unsigned addr,
                                       unsigned long long& lo,
                                       unsigned long long& hi) {
    asm volatile("ld.shared.v2.u64 {%0, %1}, [%2];"
                 : "=l"(lo), "=l"(hi) : "r"(addr));
}

__global__ void __launch_bounds__(kThreads, 5)
dgb_kernel(const float* __restrict__ feat, float* __restrict__ out) {
    __shared__ float sm[kWarpsPerCta * kWarpWords];

    const int lane = threadIdx.x & 31;
    const int w = threadIdx.x >> 5;
    const int item = blockIdx.x * kWarpsPerCta + w;     // < 65536
    const int b = item >> 11;                           // / kT
    const int t = item & (kT - 1);

    float* __restrict__ Fw = sm + w * kWarpWords;
    float* __restrict__ G = Fw;                         // aliases F (see above)
    const unsigned fb = (unsigned)__cvta_generic_to_shared(Fw);

    // ---- zero pad row 19 (512 B: one st.shared.v4 per lane) ----
    {
        unsigned z = 0u;
        unsigned dst = fb + 19u * 512u + (unsigned)(lane << 4);
        asm volatile("st.shared.v4.b32 [%0], {%1,%1,%1,%1};"
                     :: "r"(dst), "r"(z) : "memory");
    }

    // ---- stage 19 rows GMEM -> SMEM (cp.async 16B, granule swizzle) ----
    // Row n, logical granule c stored at physical granule (c ^ 2*(n/5)).
    {
        const float* src0 =
            feat + (((size_t)b * kN) * kT + (size_t)t) * kD + lane * 4;
#pragma unroll
        for (int n = 0; n < kN; ++n) {
            unsigned dst = fb + (unsigned)(n * 512 + ((lane ^ (2 * (n / 5))) << 4));
            const float* src = src0 + (size_t)n * (kT * kD);
            asm volatile("cp.async.cg.shared.global [%0], [%1], 16;"
                         :: "r"(dst), "l"(src) : "memory");
        }
        asm volatile("cp.async.commit_group;" ::: "memory");
        asm volatile("cp.async.wait_group 0;" ::: "memory");
    }
    __syncwarp();

    // ---- tile map: 10 upper-tri 5x5 tiles over the 20x20 grid ----
    // lane: tile = min(lane>>1, 9), h = lane&1. Lanes 20-31 clamp to tile 9
    // (pure duplicates -> broadcast, stores predicated off).
    const int s2 = lane >> 1;
    const int tile = (s2 > 9) ? 9 : s2;
    const int h = lane & 1;
    int a, q;
    if (tile < 4)      { a = 0; q = tile; }
    else if (tile < 7) { a = 1; q = tile - 3; }
    else if (tile < 9) { a = 2; q = tile - 5; }
    else               { a = 3; q = 3; }

    const unsigned baseA = fb + (unsigned)(a * 5 * 512);
    const unsigned baseB = fb + (unsigned)(q * 5 * 512);
    const int ka = 2 * a, kq = 2 * q;

    unsigned long long acc[5][5];
#pragma unroll
    for (int r = 0; r < 5; ++r)
#pragma unroll
        for (int c = 0; c < 5; ++c) acc[r][c] = 0ull;

    // Lane covers granules g = 2*it + h  (16 granules x 4 floats = 64 d).
    // Per LDS: distinct addrs = 4 groups x 2 halves = 8 x 16B = 128B = 1 wf,
    // bank-group k = 2*((it^grp)&3) + h  -> bijective, conflict-free.
#pragma unroll
    for (int it = 0; it < 16; ++it) {
        const int g = 2 * it + h;
        const unsigned offA = (unsigned)((g ^ ka) << 4);
        const unsigned offB = (unsigned)((g ^ kq) << 4);
        unsigned long long alo[5], ahi[5];
#pragma unroll
        for (int r = 0; r < 5; ++r)
            lds128(baseA + (unsigned)(r * 512) + offA, alo[r], ahi[r]);
#pragma unroll
        for (int c = 0; c < 5; ++c) {
            unsigned long long blo, bhi;
            lds128(baseB + (unsigned)(c * 512) + offB, blo, bhi);
#pragma unroll
            for (int r = 0; r < 5; ++r) {
                acc[r][c] = ffma2(alo[r], blo, acc[r][c]);
                acc[r][c] = ffma2(ahi[r], bhi, acc[r][c]);
            }
        }
    }
    __syncwarp();   // all gram loads done in all lanes before G overwrites F

    // ---- reduce halves; fused scatter: h=0 writes (R,C), h=1 writes (C,R) ----
#pragma unroll
    for (int r = 0; r < 5; ++r) {
#pragma unroll
        for (int c = 0; c < 5; ++c) {
            float2 p = unpack2(acc[r][c]);
            float v = p.x + p.y;
            v += __shfl_xor_sync(0xffffffffu, v, 1);
            const int R = 5 * a + r, C = 5 * q + c;
            if (lane < 20 && R < kN && C < kN) {
                const int idx = h ? (C * kGS + R) : (R * kGS + C);
                G[idx] = v;
            }
        }
    }
    __syncwarp();

    // ---- epilogue: lane i owns row i (lanes >= 19 clamp -> broadcast) ----
    {
        const int ir = (lane < kN) ? lane : (kN - 1);
        float g[kN];
#pragma unroll
        for (int j = 0; j < kN; ++j) g[j] = G[ir * kGS + j];

        const float rinv = rsqrtf(fmaxf(g[ir], 1e-24f));
        const float ri10 = rinv * kInvTemp;

        float m = -1e30f;
#pragma unroll
        for (int j = 0; j < kN; ++j) {
            float rj = __shfl_sync(0xffffffffu, rinv, j);
            g[j] = g[j] * ri10 * rj;
            m = fmaxf(m, g[j]);
        }
        float sum = 0.f;
#pragma unroll
        for (int j = 0; j < kN; ++j) {
            g[j] = __expf(g[j] - m);
            sum += g[j];
        }
        const float inv = 1.0f / sum;

        float t1 = -1e30f, t2 = -1e30f, t3 = -1e30f;
#pragma unroll
        for (int j = 0; j < kN; ++j) {
            float v = g[j] * inv;
            g[j] = v;
            if (v > t1)      { t3 = t2; t2 = t1; t1 = v; }
            else if (v > t2) { t3 = t2; t2 = v; }
            else if (v > t3) { t3 = v; }
        }

        __syncwarp();   // row reads complete before sparse overwrite
        if (lane < kN) {
#pragma unroll
            for (int j = 0; j < kN; ++j) {
                float v = g[j];
                G[lane * kGS + j] = (v >= t3 && v > kThresh) ? v : 0.0f;
            }
        }
    }
    __syncwarp();

    // ---- symmetrize + coalesced store: 361 floats per item ----
    {
        float* dst = out + (size_t)item * (kN * kN);
#pragma unroll
        for (int k = lane; k < kN * kN; k += 32) {
            int ii = k / kN;
            int jj = k - ii * kN;
            dst[k] = 0.5f * (G[ii * kGS + jj] + G[jj * kGS + ii]);
        }
    }
}

}  // namespace

extern "C" void kernel_launch(void* const* d_in, const int* in_sizes, int n_in,
                              void* d_out, int out_size) {
    (void)in_sizes; (void)n_in; (void)out_size;
    const float* feat = (const float*)d_in[0];
    float* out = (float*)d_out;
    dgb_kernel<<<kGrid, kThreads>>>(feat, out);
}

// round 11
// speedup vs baseline: 1.5741x; 1.5741x over previous
#include <cuda_runtime.h>
#include <cstdint>
#include <cstddef>

// ---------------------------------------------------------------------------
// DynamicGraphBuilder: per (b,t) item: 19x19 cosine similarity -> /0.1 ->
// softmax -> top-3 keep -> threshold 1e-4 -> 0.5*(A+A^T).
// One warp per item. F staged in SMEM (4 groups of 5 rows, XOR granule
// swizzle key=2*grp). Gram via 10 upper-tri 5x5 register tiles x 2 d-halves
// (20 lanes), every operand LDS.128 = exactly 1 conflict-free wavefront.
// G aliases F (F dead after gram loop). 4 CTAs/SM (128-reg budget: the
// 25 x u64 accumulators must stay in registers -- at 5 CTAs ptxas spills).
// ---------------------------------------------------------------------------

namespace {

constexpr int kN = 19;
constexpr int kT = 2048;
constexpr int kD = 128;
constexpr int kItems = 32 * kT;            // 65536
constexpr int kWarpsPerCta = 4;
constexpr int kThreads = kWarpsPerCta * 32;
constexpr int kGrid = kItems / kWarpsPerCta;

constexpr float kInvTemp = 10.0f;          // 1 / 0.1
constexpr float kThresh = 1e-4f;

// Per-warp SMEM: F = 20 rows x 128 floats (row 19 zero pad), 2560 words.
// G (19 x stride 21 = 399 words) ALIASES the start of F: F is dead before
// the first G write (scatter happens after the full gram loop).
constexpr int kGS = 21;
constexpr int kWarpWords = 2560;           // 10240 B / warp, 40960 B / CTA

__device__ __forceinline__ unsigned long long ffma2(unsigned long long a,
                                                    unsigned long long b,
                                                    unsigned long long c) {
    unsigned long long d;
    asm("fma.rn.f32x2 %0, %1, %2, %3;" : "=l"(d) : "l"(a), "l"(b), "l"(c));
    return d;
}

__device__ __forceinline__ float2 unpack2(unsigned long long v) {
    float2 r;
    asm("mov.b64 {%0, %1}, %2;" : "=f"(r.x), "=f"(r.y) : "l"(v));
    return r;
}

__device__ __forceinline__ void lds128(unsigned addr,
                                       unsigned long long& lo,
                                       unsigned long long& hi) {
    asm volatile("ld.shared.v2.u64 {%0, %1}, [%2];"
                 : "=l"(lo), "=l"(hi) : "r"(addr));
}

__global__ void __launch_bounds__(kThreads, 4)
dgb_kernel(const float* __restrict__ feat, float* __restrict__ out) {
    __shared__ float sm[kWarpsPerCta * kWarpWords];

    const int lane = threadIdx.x & 31;
    const int w = threadIdx.x >> 5;
    const int item = blockIdx.x * kWarpsPerCta + w;     // < 65536
    const int b = item >> 11;                           // / kT
    const int t = item & (kT - 1);

    float* __restrict__ Fw = sm + w * kWarpWords;
    float* __restrict__ G = Fw;                         // aliases F (see above)
    const unsigned fb = (unsigned)__cvta_generic_to_shared(Fw);

    // ---- zero pad row 19 (512 B: one st.shared.v4 per lane) ----
    {
        unsigned z = 0u;
        unsigned dst = fb + 19u * 512u + (unsigned)(lane << 4);
        asm volatile("st.shared.v4.b32 [%0], {%1,%1,%1,%1};"
                     :: "r"(dst), "r"(z) : "memory");
    }

    // ---- stage 19 rows GMEM -> SMEM (cp.async 16B, granule swizzle) ----
    // Row n, logical granule c stored at physical granule (c ^ 2*(n/5)).
    {
        const float* src0 =
            feat + (((size_t)b * kN) * kT + (size_t)t) * kD + lane * 4;
#pragma unroll
        for (int n = 0; n < kN; ++n) {
            unsigned dst = fb + (unsigned)(n * 512 + ((lane ^ (2 * (n / 5))) << 4));
            const float* src = src0 + (size_t)n * (kT * kD);
            asm volatile("cp.async.cg.shared.global [%0], [%1], 16;"
                         :: "r"(dst), "l"(src) : "memory");
        }
        asm volatile("cp.async.commit_group;" ::: "memory");
        asm volatile("cp.async.wait_group 0;" ::: "memory");
    }
    __syncwarp();

    // ---- tile map: 10 upper-tri 5x5 tiles over the 20x20 grid ----
    // lane: tile = min(lane>>1, 9), h = lane&1. Lanes 20-31 clamp to tile 9
    // (pure duplicates -> broadcast, stores predicated off).
    const int s2 = lane >> 1;
    const int tile = (s2 > 9) ? 9 : s2;
    const int h = lane & 1;
    int a, q;
    if (tile < 4)      { a = 0; q = tile; }
    else if (tile < 7) { a = 1; q = tile - 3; }
    else if (tile < 9) { a = 2; q = tile - 5; }
    else               { a = 3; q = 3; }

    const unsigned baseA = fb + (unsigned)(a * 5 * 512);
    const unsigned baseB = fb + (unsigned)(q * 5 * 512);
    const int ka = 2 * a, kq = 2 * q;

    unsigned long long acc[5][5];
#pragma unroll
    for (int r = 0; r < 5; ++r)
#pragma unroll
        for (int c = 0; c < 5; ++c) acc[r][c] = 0ull;

    // Lane covers granules g = 2*it + h  (16 granules x 4 floats = 64 d).
    // Per LDS: distinct addrs = 4 groups x 2 halves = 8 x 16B = 128B = 1 wf,
    // bank-group k = 2*((it^grp)&3) + h  -> bijective, conflict-free.
#pragma unroll
    for (int it = 0; it < 16; ++it) {
        const int g = 2 * it + h;
        const unsigned offA = (unsigned)((g ^ ka) << 4);
        const unsigned offB = (unsigned)((g ^ kq) << 4);
        unsigned long long alo[5], ahi[5];
#pragma unroll
        for (int r = 0; r < 5; ++r)
            lds128(baseA + (unsigned)(r * 512) + offA, alo[r], ahi[r]);
#pragma unroll
        for (int c = 0; c < 5; ++c) {
            unsigned long long blo, bhi;
            lds128(baseB + (unsigned)(c * 512) + offB, blo, bhi);
#pragma unroll
            for (int r = 0; r < 5; ++r) {
                acc[r][c] = ffma2(alo[r], blo, acc[r][c]);
                acc[r][c] = ffma2(ahi[r], bhi, acc[r][c]);
            }
        }
    }
    __syncwarp();   // all gram loads done in all lanes before G overwrites F

    // ---- reduce halves; fused scatter: h=0 writes (R,C), h=1 writes (C,R) ----
#pragma unroll
    for (int r = 0; r < 5; ++r) {
#pragma unroll
        for (int c = 0; c < 5; ++c) {
            float2 p = unpack2(acc[r][c]);
            float v = p.x + p.y;
            v += __shfl_xor_sync(0xffffffffu, v, 1);
            const int R = 5 * a + r, C = 5 * q + c;
            if (lane < 20 && R < kN && C < kN) {
                const int idx = h ? (C * kGS + R) : (R * kGS + C);
                G[idx] = v;
            }
        }
    }
    __syncwarp();

    // ---- epilogue: lane i owns row i (lanes >= 19 clamp -> broadcast) ----
    {
        const int ir = (lane < kN) ? lane : (kN - 1);
        float g[kN];
#pragma unroll
        for (int j = 0; j < kN; ++j) g[j] = G[ir * kGS + j];

        const float rinv = rsqrtf(fmaxf(g[ir], 1e-24f));
        const float ri10 = rinv * kInvTemp;

        float m = -1e30f;
#pragma unroll
        for (int j = 0; j < kN; ++j) {
            float rj = __shfl_sync(0xffffffffu, rinv, j);
            g[j] = g[j] * ri10 * rj;
            m = fmaxf(m, g[j]);
        }
        float sum = 0.f;
#pragma unroll
        for (int j = 0; j < kN; ++j) {
            g[j] = __expf(g[j] - m);
            sum += g[j];
        }
        const float inv = 1.0f / sum;

        float t1 = -1e30f, t2 = -1e30f, t3 = -1e30f;
#pragma unroll
        for (int j = 0; j < kN; ++j) {
            float v = g[j] * inv;
            g[j] = v;
            if (v > t1)      { t3 = t2; t2 = t1; t1 = v; }
            else if (v > t2) { t3 = t2; t2 = v; }
            else if (v > t3) { t3 = v; }
        }

        __syncwarp();   // row reads complete before sparse overwrite
        if (lane < kN) {
#pragma unroll
            for (int j = 0; j < kN; ++j) {
                float v = g[j];
                G[lane * kGS + j] = (v >= t3 && v > kThresh) ? v : 0.0f;
            }
        }
    }
    __syncwarp();

    // ---- symmetrize + coalesced store: 361 floats per item ----
    {
        float* dst = out + (size_t)item * (kN * kN);
#pragma unroll
        for (int k = lane; k < kN * kN; k += 32) {
            int ii = k / kN;
            int jj = k - ii * kN;
            dst[k] = 0.5f * (G[ii * kGS + jj] + G[jj * kGS + ii]);
        }
    }
}

}  // namespace

extern "C" void kernel_launch(void* const* d_in, const int* in_sizes, int n_in,
                              void* d_out, int out_size) {
    (void)in_sizes; (void)n_in; (void)out_size;
    const float* feat = (const float*)d_in[0];
    float* out = (float*)d_out;
    dgb_kernel<<<kGrid, kThreads>>>(feat, out);
}